// round 8
// baseline (speedup 1.0000x reference)
#include <cuda_runtime.h>

// Fixed shapes
#define NB 4096
#define NS 200
#define XST 212   // XsT row stride in floats

// smem offsets (bytes), 16B-aligned
#define OFF_MSP   0        // Msplat: 64 rows x 64 u64 (splat, chunk-permuted) 32768
#define OFF_W2D   32768    // W2dup:  64 rows x 32 u64 (splat, XOR swizzle)   16384
#define OFF_CSD   49152    // csdup:  64 u64 (c_b splat)                        512
#define OFF_B2D   49664    // b2dup:  32 u64                                    256
#define OFF_W3D   49920    // w3dup:  32 u64                                    256
#define OFF_BNSC  50176    // 128 f                                             512
#define OFF_BNSH  50688    // 128 f                                             512
#define OFF_QS    51200    // 64 f                                              256
#define OFF_LG    51456    // 200 f (pad 816)
#define OFF_WE    52272    // 200 f (pad 816)
#define OFF_RED   53088    // red[0]=max red[1]=1/sum red[2]=b3 (pad 32)
#define OFF_XST   53120    // 64*212*4 = 54272
#define SMEM_BYTES 107456

typedef unsigned long long u64;

__device__ __forceinline__ u64 pack2(float a, float b) {
    u64 r;
    asm("mov.b64 %0, {%1, %2};" : "=l"(r)
        : "r"(__float_as_uint(a)), "r"(__float_as_uint(b)));
    return r;
}
__device__ __forceinline__ void ffma2(u64& d, u64 a, u64 b) {
    asm("fma.rn.f32x2 %0, %1, %2, %0;" : "+l"(d) : "l"(a), "l"(b));
}
__device__ __forceinline__ void add2(u64& d, u64 a) {
    asm("add.rn.f32x2 %0, %0, %1;" : "+l"(d) : "l"(a));
}
__device__ __forceinline__ float lo32(u64 v) { return __uint_as_float((unsigned)v); }
__device__ __forceinline__ float hi32(u64 v) { return __uint_as_float((unsigned)(v >> 32)); }
__device__ __forceinline__ u64 relu2(u64 v) {
    return pack2(fmaxf(lo32(v), 0.f), fmaxf(hi32(v), 0.f));
}
__device__ __forceinline__ u64 shflx64(u64 v, int m, unsigned msk) {
    double d = __longlong_as_double((long long)v);
    d = __shfl_xor_sync(msk, d, m);
    return (u64)__double_as_longlong(d);
}

extern __shared__ unsigned char smem_raw[];

__global__ void __launch_bounds__(512, 2) din_user_rep_kernel(
    const float* __restrict__ em,   const float* __restrict__ eu,
    const float* __restrict__ Xu,   const float* __restrict__ W1,
    const float* __restrict__ b1,   const float* __restrict__ W2,
    const float* __restrict__ b2,   const float* __restrict__ W3,
    const float* __restrict__ b3,   const float* __restrict__ gamma,
    const float* __restrict__ beta, const float* __restrict__ mmean,
    const float* __restrict__ mvar, float* __restrict__ out)
{
    const int t = threadIdx.x;
    const int b = blockIdx.x;

    float* Msp  = (float*)(smem_raw + OFF_MSP);
    float* W2d  = (float*)(smem_raw + OFF_W2D);
    u64*   csd  = (u64*)  (smem_raw + OFF_CSD);
    u64*   b2d  = (u64*)  (smem_raw + OFF_B2D);
    u64*   w3d  = (u64*)  (smem_raw + OFF_W3D);
    float* bnsc = (float*)(smem_raw + OFF_BNSC);
    float* bnsh = (float*)(smem_raw + OFF_BNSH);
    float* qs   = (float*)(smem_raw + OFF_QS);
    float* lg   = (float*)(smem_raw + OFF_LG);
    float* we   = (float*)(smem_raw + OFF_WE);
    float* red  = (float*)(smem_raw + OFF_RED);
    float* XsT  = (float*)(smem_raw + OFF_XST);

    // ---- Phase 0 ----
    if (t < 64)  qs[t] = em[(size_t)b * 64 + t];
    if (t < 128) {
        float sc = gamma[t] * rsqrtf(mvar[t] + 1e-3f);
        bnsc[t] = sc;
        bnsh[t] = beta[t] - mmean[t] * sc;
    }
    if (t < 32) {
        float w3v = W3[t], b2v = b2[t];
        w3d[t] = pack2(w3v, w3v);
        b2d[t] = pack2(b2v, b2v);
    }
    if (t == 0) red[2] = b3[0];

    // Xu transpose staging (coalesced global -> contiguous STS.128)
    const float* Xb = Xu + (size_t)b * (NS * 64);
    for (int e = t; e < 64 * 50; e += 512) {
        int d = e & 63, sc = e >> 6;
        float x0 = Xb[(4 * sc + 0) * 64 + d];
        float x1 = Xb[(4 * sc + 1) * 64 + d];
        float x2 = Xb[(4 * sc + 2) * 64 + d];
        float x3 = Xb[(4 * sc + 3) * 64 + d];
        *(float4*)(XsT + d * XST + 4 * sc) = make_float4(x0, x1, x2, x3);
    }
    __syncthreads();   // qs ready

    // ---- Phase 1: splat-duplicated folded weights ----
    // Msplat[k][j] = (m,m), m = W1b - W1c + q_k*W1d.  Chunk c=j>>1 stored at
    // slot 8*(c&3)+(c>>2): lane ct's 4 loads (chunks 4ct+L) land at slots
    // 8L+ct -> 8 distinct bank quads per load. Row = 128 floats.
    for (int e = t; e < 4096; e += 512) {
        int k = e >> 6, j = e & 63;
        float m = W1[(64 + k) * 64 + j] - W1[(128 + k) * 64 + j]
                + qs[k] * W1[(192 + k) * 64 + j];
        int c = j >> 1;
        int slot = 8 * (c & 3) + (c >> 2);
        *(float2*)(Msp + k * 128 + slot * 4 + (j & 1) * 2) = make_float2(m, m);
    }
    // W2dup[k][j] = (w,w); chunk (j>>1) XOR (k>>3 & 7). Row = 64 floats.
    for (int e = t; e < 2048; e += 512) {
        int k = e >> 5, j = e & 31;
        float w = W2[e];
        int slot = (j >> 1) ^ ((k >> 3) & 7);
        *(float2*)(W2d + k * 64 + slot * 4 + (j & 1) * 2) = make_float2(w, w);
    }
    // csdup[j] = (c_b[j], c_b[j])
    if (t < 64) {
        float c0 = b1[t];
        #pragma unroll 4
        for (int k = 0; k < 64; k++)
            c0 += qs[k] * (W1[k * 64 + t] + W1[(128 + k) * 64 + t]);
        csd[t] = pack2(c0, c0);
    }
    __syncthreads();

    // ---- Phase 2: 4x8 register-tiled MLP (400 active threads) ----
    // rt = t>>3 (0..49), ct = t&7. Rows s0..s0+3 as 2 row-pairs; cols 8ct..8ct+7.
    if (t < 400) {
        const int rt = t >> 3, ct = t & 7;
        const int s0 = 4 * rt;
        const unsigned gmask = 0xFFu << ((t & 31) & 24);

        // Layer 1: acc[rp][jj] = (h1[s0+2rp][8ct+jj], h1[s0+2rp+1][8ct+jj])
        u64 acc[2][8];
        #pragma unroll
        for (int jj = 0; jj < 8; jj++) {
            u64 cv = csd[8 * ct + jj];
            acc[0][jj] = cv; acc[1][jj] = cv;
        }
        const float* xk = XsT + s0;
        const float* mk = Msp + 4 * ct;

        #pragma unroll 4
        for (int k = 0; k < 64; k++) {
            ulonglong2 xu = *(const ulonglong2*)(xk + k * XST);  // 2 row-pairs
            const float* mr = mk + k * 128;
            ulonglong2 m0 = *(const ulonglong2*)(mr);            // j 8ct+0,1
            ulonglong2 m1 = *(const ulonglong2*)(mr + 32);       // j 8ct+2,3
            ulonglong2 m2 = *(const ulonglong2*)(mr + 64);       // j 8ct+4,5
            ulonglong2 m3 = *(const ulonglong2*)(mr + 96);       // j 8ct+6,7
            ffma2(acc[0][0], xu.x, m0.x); ffma2(acc[1][0], xu.y, m0.x);
            ffma2(acc[0][1], xu.x, m0.y); ffma2(acc[1][1], xu.y, m0.y);
            ffma2(acc[0][2], xu.x, m1.x); ffma2(acc[1][2], xu.y, m1.x);
            ffma2(acc[0][3], xu.x, m1.y); ffma2(acc[1][3], xu.y, m1.y);
            ffma2(acc[0][4], xu.x, m2.x); ffma2(acc[1][4], xu.y, m2.x);
            ffma2(acc[0][5], xu.x, m2.y); ffma2(acc[1][5], xu.y, m2.y);
            ffma2(acc[0][6], xu.x, m3.x); ffma2(acc[1][6], xu.y, m3.x);
            ffma2(acc[0][7], xu.x, m3.y); ffma2(acc[1][7], xu.y, m3.y);
        }
        // relu(h1) in place
        #pragma unroll
        for (int rp = 0; rp < 2; rp++)
            #pragma unroll
            for (int jj = 0; jj < 8; jj++) acc[rp][jj] = relu2(acc[rp][jj]);

        // Layer 2+3: lane's k-rows = 8ct..8ct+7 (== its h1 j's). jc = 4 j's.
        // hb[rp][jo] accumulates row-pairs for j = 4jc+jo; reduce-scatter over
        // the 8-lane ct group; duplicated-j double count fixed by *0.5.
        u64 lacc[2] = {0, 0};
        const float* w2base = W2d + (8 * ct) * 64;
        #pragma unroll 1
        for (int jc = 0; jc < 8; jc++) {
            u64 hb[2][4] = {{0,0,0,0},{0,0,0,0}};
            const int sl0 = ((2 * jc) ^ ct) * 4;
            const int sl1 = ((2 * jc + 1) ^ ct) * 4;
            #pragma unroll
            for (int jj = 0; jj < 8; jj++) {
                const float* wr = w2base + jj * 64;
                ulonglong2 wa = *(const ulonglong2*)(wr + sl0);  // j 4jc+0,1
                ulonglong2 wb = *(const ulonglong2*)(wr + sl1);  // j 4jc+2,3
                u64 h0 = acc[0][jj], h1 = acc[1][jj];
                ffma2(hb[0][0], h0, wa.x); ffma2(hb[1][0], h1, wa.x);
                ffma2(hb[0][1], h0, wa.y); ffma2(hb[1][1], h1, wa.y);
                ffma2(hb[0][2], h0, wb.x); ffma2(hb[1][2], h1, wb.x);
                ffma2(hb[0][3], h0, wb.y); ffma2(hb[1][3], h1, wb.y);
            }
            // reduce-scatter over ct lanes
            const bool o1 = (ct & 1), o2 = (ct & 2);
            u64 hbr[2];
            #pragma unroll
            for (int rp = 0; rp < 2; rp++) {
                u64 k0 = o1 ? hb[rp][2] : hb[rp][0];
                u64 k1 = o1 ? hb[rp][3] : hb[rp][1];
                u64 s0_ = o1 ? hb[rp][0] : hb[rp][2];
                u64 s1_ = o1 ? hb[rp][1] : hb[rp][3];
                add2(k0, shflx64(s0_, 1, gmask));
                add2(k1, shflx64(s1_, 1, gmask));
                u64 k2 = o2 ? k1 : k0;
                u64 s2 = o2 ? k0 : k1;
                add2(k2, shflx64(s2, 2, gmask));
                add2(k2, shflx64(k2, 4, gmask));
                hbr[rp] = k2;
            }
            const int jown = jc * 4 + 2 * (ct & 1) + ((ct >> 1) & 1);
            u64 b2v = b2d[jown], w3v = w3d[jown];
            #pragma unroll
            for (int rp = 0; rp < 2; rp++) {
                u64 h = hbr[rp];
                add2(h, b2v);
                ffma2(lacc[rp], relu2(h), w3v);
            }
        }
        // final reduce over ct group; each j counted twice -> *0.5
        #pragma unroll
        for (int rp = 0; rp < 2; rp++) {
            add2(lacc[rp], shflx64(lacc[rp], 1, gmask));
            add2(lacc[rp], shflx64(lacc[rp], 2, gmask));
            add2(lacc[rp], shflx64(lacc[rp], 4, gmask));
        }
        if (ct == 0) {
            float b3v = red[2];
            lg[s0 + 0] = lo32(lacc[0]) * 0.5f + b3v;
            lg[s0 + 1] = hi32(lacc[0]) * 0.5f + b3v;
            lg[s0 + 2] = lo32(lacc[1]) * 0.5f + b3v;
            lg[s0 + 3] = hi32(lacc[1]) * 0.5f + b3v;
        }
    }
    __syncthreads();

    // ---- Softmax reduction (warp 0) ----
    if (t < 32) {
        float m = -3.0e38f;
        for (int r = t; r < NS; r += 32) m = fmaxf(m, lg[r]);
        #pragma unroll
        for (int o = 16; o; o >>= 1) m = fmaxf(m, __shfl_xor_sync(0xffffffffu, m, o));
        float ssum = 0.f;
        for (int r = t; r < NS; r += 32) ssum += __expf(lg[r] - m);
        #pragma unroll
        for (int o = 16; o; o >>= 1) ssum += __shfl_xor_sync(0xffffffffu, ssum, o);
        if (t == 0) { red[0] = m; red[1] = 1.f / ssum; }
    }
    __syncthreads();
    if (t < NS) we[t] = __expf(lg[t] - red[0]) * red[1];
    __syncthreads();

    // ---- Pool + BN + output: out row = [bn(pooled), bn(em), eu] ----
    float* ob = out + (size_t)b * 192;
    if (t < 64) {
        const float4* xr = (const float4*)(XsT + t * XST);
        const float4* wv = (const float4*)we;
        float p = 0.f;
        #pragma unroll 5
        for (int sc = 0; sc < 50; sc++) {
            float4 x = xr[sc], w = wv[sc];
            p += x.x * w.x + x.y * w.y + x.z * w.z + x.w * w.w;
        }
        ob[t] = p * bnsc[t] + bnsh[t];
    } else if (t < 128) {
        ob[t] = qs[t - 64] * bnsc[t] + bnsh[t];
    } else if (t < 192) {
        ob[t] = eu[(size_t)b * 64 + (t - 128)];
    }
}

extern "C" void kernel_launch(void* const* d_in, const int* in_sizes, int n_in,
                              void* d_out, int out_size) {
    (void)in_sizes; (void)n_in; (void)out_size;
    cudaFuncSetAttribute(din_user_rep_kernel,
                         cudaFuncAttributeMaxDynamicSharedMemorySize, SMEM_BYTES);
    din_user_rep_kernel<<<NB, 512, SMEM_BYTES>>>(
        (const float*)d_in[0],  // em
        (const float*)d_in[1],  // eu
        (const float*)d_in[2],  // Xu
        (const float*)d_in[3],  // W1
        (const float*)d_in[4],  // b1
        (const float*)d_in[5],  // W2
        (const float*)d_in[6],  // b2
        (const float*)d_in[7],  // W3
        (const float*)d_in[8],  // b3
        (const float*)d_in[9],  // gamma
        (const float*)d_in[10], // beta
        (const float*)d_in[11], // mov_mean
        (const float*)d_in[12], // mov_var
        (float*)d_out);
}

// round 10
// speedup vs baseline: 1.7277x; 1.7277x over previous
#include <cuda_runtime.h>
#include <cuda_bf16.h>
#include <cstdint>

// Fixed shapes
#define NB 4096
#define NS 200
#define SA 144        // row stride (bytes) for all mma tiles; 16B-aligned, 4i bank phase

// smem layout (bytes)
#define OFF_AHI   0        // X hi bf16: 208 rows x 144B  (29952)
#define OFF_ALO   29952    // X lo
#define OFF_B1HI  59904    // M_b^T hi: 64 rows x 144B    (9216)
#define OFF_B1LO  69120
#define OFF_B2HI  78336    // W2^T hi: 32 rows x 144B     (4608)
#define OFF_B2LO  82944
#define OFF_QS    87552    // 64 f
#define OFF_CS    87808    // 64 f (c_b)
#define OFF_B2S   88064    // 32 f
#define OFF_W3S   88192    // 32 f
#define OFF_BNSC  88320    // 128 f
#define OFF_BNSH  88832    // 128 f
#define OFF_LG    89344    // 200 f
#define OFF_WE    90144    // 200 f
#define OFF_PP    90944    // 256 f
#define OFF_RED   91968    // red[2]=b3, red[0]=max, red[1]=1/sum
#define SMEM_BYTES 92032

static __device__ __forceinline__ uint32_t s2u(const void* p) {
    uint32_t a;
    asm("{ .reg .u64 t; cvta.to.shared.u64 t, %1; cvt.u32.u64 %0, t; }"
        : "=r"(a) : "l"(p));
    return a;
}

#define LDSM_X4(r0, r1, r2, r3, addr) \
    asm volatile("ldmatrix.sync.aligned.m8n8.x4.shared.b16 {%0,%1,%2,%3}, [%4];" \
                 : "=r"(r0), "=r"(r1), "=r"(r2), "=r"(r3) : "r"(addr))
#define LDSM_X2(r0, r1, addr) \
    asm volatile("ldmatrix.sync.aligned.m8n8.x2.shared.b16 {%0,%1}, [%2];" \
                 : "=r"(r0), "=r"(r1) : "r"(addr))
#define MMA_BF16(c, a0, a1, a2, a3, b0, b1) \
    asm volatile("mma.sync.aligned.m16n8k16.row.col.f32.bf16.bf16.f32 " \
                 "{%0,%1,%2,%3}, {%4,%5,%6,%7}, {%8,%9}, {%0,%1,%2,%3};" \
                 : "+f"((c)[0]), "+f"((c)[1]), "+f"((c)[2]), "+f"((c)[3]) \
                 : "r"(a0), "r"(a1), "r"(a2), "r"(a3), "r"(b0), "r"(b1))

// split pair (x, y) -> packed bf16x2 hi word + lo (residual) word
static __device__ __forceinline__ void split2(float x, float y,
                                              uint32_t& h, uint32_t& l) {
    __nv_bfloat16 xh = __float2bfloat16(x), yh = __float2bfloat16(y);
    __nv_bfloat16 xl = __float2bfloat16(x - __bfloat162float(xh));
    __nv_bfloat16 yl = __float2bfloat16(y - __bfloat162float(yh));
    h = (uint32_t)__bfloat16_as_ushort(xh) | ((uint32_t)__bfloat16_as_ushort(yh) << 16);
    l = (uint32_t)__bfloat16_as_ushort(xl) | ((uint32_t)__bfloat16_as_ushort(yl) << 16);
}

extern __shared__ unsigned char smem_raw[];

__global__ void __launch_bounds__(256, 2) din_user_rep_mma(
    const float* __restrict__ em,   const float* __restrict__ eu,
    const float* __restrict__ Xu,   const float* __restrict__ W1,
    const float* __restrict__ b1,   const float* __restrict__ W2,
    const float* __restrict__ b2,   const float* __restrict__ W3,
    const float* __restrict__ b3,   const float* __restrict__ gamma,
    const float* __restrict__ beta, const float* __restrict__ mmean,
    const float* __restrict__ mvar, float* __restrict__ out)
{
    const int t = threadIdx.x;
    const int b = blockIdx.x;
    const uint32_t sb = s2u(smem_raw);

    float* qs   = (float*)(smem_raw + OFF_QS);
    float* cs   = (float*)(smem_raw + OFF_CS);
    float* b2s  = (float*)(smem_raw + OFF_B2S);
    float* w3s  = (float*)(smem_raw + OFF_W3S);
    float* bnsc = (float*)(smem_raw + OFF_BNSC);
    float* bnsh = (float*)(smem_raw + OFF_BNSH);
    float* lg   = (float*)(smem_raw + OFF_LG);
    float* we   = (float*)(smem_raw + OFF_WE);
    float* pp   = (float*)(smem_raw + OFF_PP);
    float* red  = (float*)(smem_raw + OFF_RED);

    // ---- Phase 0: vectors + X split + W2^T split + zero pad ----
    if (t < 64)  qs[t] = em[(size_t)b * 64 + t];
    if (t < 128) {
        float sc = gamma[t] * rsqrtf(mvar[t] + 1e-3f);
        bnsc[t] = sc;
        bnsh[t] = beta[t] - mmean[t] * sc;
    }
    if (t < 32) { w3s[t] = W3[t]; b2s[t] = b2[t]; }
    if (t == 0) red[2] = b3[0];

    {   // X: coalesced float4 read -> bf16 hi/lo pairs, row stride 144B
        const float4* Xb4 = (const float4*)(Xu + (size_t)b * (NS * 64));
        for (int e = t; e < NS * 16; e += 256) {
            int s = e >> 4, c4 = e & 15;
            float4 xv = Xb4[e];
            uint32_t h0, l0, h1, l1;
            split2(xv.x, xv.y, h0, l0);
            split2(xv.z, xv.w, h1, l1);
            *(uint2*)(smem_raw + OFF_AHI + s * SA + c4 * 8) = make_uint2(h0, h1);
            *(uint2*)(smem_raw + OFF_ALO + s * SA + c4 * 8) = make_uint2(l0, l1);
        }
    }
    // B2t[j2][k] = W2[k][j2], bf16 hi/lo
    for (int e = t; e < 2048; e += 256) {
        int j2 = e & 31, k = e >> 5;                    // coalesced W2 read
        float w = W2[k * 32 + j2];
        __nv_bfloat16 wh = __float2bfloat16(w);
        __nv_bfloat16 wl = __float2bfloat16(w - __bfloat162float(wh));
        *(uint16_t*)(smem_raw + OFF_B2HI + j2 * SA + k * 2) = __bfloat16_as_ushort(wh);
        *(uint16_t*)(smem_raw + OFF_B2LO + j2 * SA + k * 2) = __bfloat16_as_ushort(wl);
    }
    // zero pad A rows 200..207
    if (t < 256) {
        int r = 200 + (t >> 5), w = t & 31;
        ((uint32_t*)(smem_raw + OFF_AHI))[(r * SA) / 4 + w] = 0;
        ((uint32_t*)(smem_raw + OFF_ALO))[(r * SA) / 4 + w] = 0;
    }
    __syncthreads();   // qs ready

    // ---- Phase 1: B1t[j][k] = M_b^T (fold) + c_b ----
    for (int e = t; e < 4096; e += 256) {
        int j = e & 63, k = e >> 6;                     // coalesced W1 reads
        float m = W1[(64 + k) * 64 + j] - W1[(128 + k) * 64 + j]
                + qs[k] * W1[(192 + k) * 64 + j];
        __nv_bfloat16 mh = __float2bfloat16(m);
        __nv_bfloat16 ml = __float2bfloat16(m - __bfloat162float(mh));
        *(uint16_t*)(smem_raw + OFF_B1HI + j * SA + k * 2) = __bfloat16_as_ushort(mh);
        *(uint16_t*)(smem_raw + OFF_B1LO + j * SA + k * 2) = __bfloat16_as_ushort(ml);
    }
    if (t < 64) {
        float c0 = b1[t];
        #pragma unroll 4
        for (int k = 0; k < 64; k++)
            c0 += qs[k] * (W1[k * 64 + t] + W1[(128 + k) * 64 + t]);
        cs[t] = c0;
    }
    __syncthreads();

    // ---- Per-warp MLP over 16-row m-tiles (13 tiles, warps independent) ----
    {
        const int wid = t >> 5, lane = t & 31;
        const int kp = lane & 3, rq = lane >> 2;
        // ldmatrix per-lane row offsets
        const uint32_t aRow = (uint32_t)(((lane & 7) + 8 * ((lane >> 3) & 1)) * SA
                                         + (lane >> 4) * 16);
        const uint32_t bRow = (uint32_t)((lane & 7) * SA + ((lane >> 3) & 1) * 16);
        const float b3v = red[2];

        for (int tile = wid; tile < 13; tile += 8) {
            const int m0 = tile * 16;
            const uint32_t aH = sb + OFF_AHI + m0 * SA + aRow;
            const uint32_t aL = sb + OFF_ALO + m0 * SA + aRow;
            const uint32_t bH = sb + OFF_B1HI + bRow;
            const uint32_t bL = sb + OFF_B1LO + bRow;

            // Layer 1: C1[16 x 64] = X_tile @ M_b  (3-term bf16 split)
            float acc[8][4];
            #pragma unroll
            for (int nt = 0; nt < 8; nt++)
                #pragma unroll
                for (int i = 0; i < 4; i++) acc[nt][i] = 0.f;

            #pragma unroll
            for (int kc = 0; kc < 4; kc++) {
                uint32_t ah0, ah1, ah2, ah3, al0, al1, al2, al3;
                LDSM_X4(ah0, ah1, ah2, ah3, aH + kc * 32);
                LDSM_X4(al0, al1, al2, al3, aL + kc * 32);
                #pragma unroll
                for (int nt = 0; nt < 8; nt++) {
                    uint32_t bh0, bh1, bl0, bl1;
                    LDSM_X2(bh0, bh1, bH + nt * (8 * SA) + kc * 32);
                    LDSM_X2(bl0, bl1, bL + nt * (8 * SA) + kc * 32);
                    MMA_BF16(acc[nt], ah0, ah1, ah2, ah3, bh0, bh1);
                    MMA_BF16(acc[nt], ah0, ah1, ah2, ah3, bl0, bl1);
                    MMA_BF16(acc[nt], al0, al1, al2, al3, bh0, bh1);
                }
            }

            // Epilogue 1 (registers): h1 = relu(C1 + c_b), split -> layer-2 A frags
            uint32_t hH[8][2], hL[8][2];
            #pragma unroll
            for (int nt = 0; nt < 8; nt++) {
                int j0 = 8 * nt + 2 * kp;
                float c0 = cs[j0], c1 = cs[j0 + 1];
                float e0 = fmaxf(acc[nt][0] + c0, 0.f);
                float e1 = fmaxf(acc[nt][1] + c1, 0.f);
                float e2 = fmaxf(acc[nt][2] + c0, 0.f);
                float e3 = fmaxf(acc[nt][3] + c1, 0.f);
                split2(e0, e1, hH[nt][0], hL[nt][0]);   // row r
                split2(e2, e3, hH[nt][1], hL[nt][1]);   // row r+8
            }

            // Layer 2: C2[16 x 32] = h1 @ W2 (A frags direct from registers)
            float a2c[4][4];
            #pragma unroll
            for (int nt = 0; nt < 4; nt++)
                #pragma unroll
                for (int i = 0; i < 4; i++) a2c[nt][i] = 0.f;

            const uint32_t c2H = sb + OFF_B2HI + bRow;
            const uint32_t c2L = sb + OFF_B2LO + bRow;
            #pragma unroll
            for (int kc = 0; kc < 4; kc++) {
                uint32_t a0h = hH[2 * kc][0], a1h = hH[2 * kc][1];
                uint32_t a2h = hH[2 * kc + 1][0], a3h = hH[2 * kc + 1][1];
                uint32_t a0l = hL[2 * kc][0], a1l = hL[2 * kc][1];
                uint32_t a2l = hL[2 * kc + 1][0], a3l = hL[2 * kc + 1][1];
                #pragma unroll
                for (int nt = 0; nt < 4; nt++) {
                    uint32_t bh0, bh1, bl0, bl1;
                    LDSM_X2(bh0, bh1, c2H + nt * (8 * SA) + kc * 32);
                    LDSM_X2(bl0, bl1, c2L + nt * (8 * SA) + kc * 32);
                    MMA_BF16(a2c[nt], a0h, a1h, a2h, a3h, bh0, bh1);
                    MMA_BF16(a2c[nt], a0h, a1h, a2h, a3h, bl0, bl1);
                    MMA_BF16(a2c[nt], a0l, a1l, a2l, a3l, bh0, bh1);
                }
            }

            // Epilogue 2: logits (quad reduce over kp lanes)
            float pA = 0.f, pB = 0.f;
            #pragma unroll
            for (int nt = 0; nt < 4; nt++) {
                int j0 = 8 * nt + 2 * kp;
                float bb0 = b2s[j0], bb1 = b2s[j0 + 1];
                float w0 = w3s[j0],  w1 = w3s[j0 + 1];
                pA += fmaxf(a2c[nt][0] + bb0, 0.f) * w0
                    + fmaxf(a2c[nt][1] + bb1, 0.f) * w1;
                pB += fmaxf(a2c[nt][2] + bb0, 0.f) * w0
                    + fmaxf(a2c[nt][3] + bb1, 0.f) * w1;
            }
            pA += __shfl_xor_sync(0xffffffffu, pA, 1);
            pA += __shfl_xor_sync(0xffffffffu, pA, 2);
            pB += __shfl_xor_sync(0xffffffffu, pB, 1);
            pB += __shfl_xor_sync(0xffffffffu, pB, 2);
            if (kp == 0) {
                int r0_ = m0 + rq;
                int r1_ = m0 + rq + 8;
                if (r0_ < NS) lg[r0_] = pA + b3v;
                if (r1_ < NS) lg[r1_] = pB + b3v;
            }
        }
    }
    __syncthreads();

    // ---- Softmax (warp 0) ----
    if (t < 32) {
        float m = -3.0e38f;
        for (int r = t; r < NS; r += 32) m = fmaxf(m, lg[r]);
        #pragma unroll
        for (int o = 16; o; o >>= 1) m = fmaxf(m, __shfl_xor_sync(0xffffffffu, m, o));
        float ssum = 0.f;
        for (int r = t; r < NS; r += 32) ssum += __expf(lg[r] - m);
        #pragma unroll
        for (int o = 16; o; o >>= 1) ssum += __shfl_xor_sync(0xffffffffu, ssum, o);
        if (t == 0) { red[0] = m; red[1] = 1.f / ssum; }
    }
    __syncthreads();
    if (t < NS) we[t] = __expf(lg[t] - red[0]) * red[1];
    __syncthreads();

    // ---- Pool from reconstructed X (hi+lo, exact to ~2^-17) ----
    {
        int d = t & 63, q = t >> 6;
        float p = 0.f;
        #pragma unroll 2
        for (int s = 50 * q; s < 50 * q + 50; s++) {
            uint16_t h = *(const uint16_t*)(smem_raw + OFF_AHI + s * SA + 2 * d);
            uint16_t l = *(const uint16_t*)(smem_raw + OFF_ALO + s * SA + 2 * d);
            float x = __bfloat162float(__ushort_as_bfloat16(h))
                    + __bfloat162float(__ushort_as_bfloat16(l));
            p += we[s] * x;
        }
        pp[t] = p;
    }
    __syncthreads();

    // ---- Output: [bn(pooled), bn(em), eu] ----
    float* ob = out + (size_t)b * 192;
    if (t < 64) {
        float pooled = pp[t] + pp[t + 64] + pp[t + 128] + pp[t + 192];
        ob[t] = pooled * bnsc[t] + bnsh[t];
    } else if (t < 128) {
        ob[t] = qs[t - 64] * bnsc[t] + bnsh[t];
    } else if (t < 192) {
        ob[t] = eu[(size_t)b * 64 + (t - 128)];
    }
}

extern "C" void kernel_launch(void* const* d_in, const int* in_sizes, int n_in,
                              void* d_out, int out_size) {
    (void)in_sizes; (void)n_in; (void)out_size;
    cudaFuncSetAttribute(din_user_rep_mma,
                         cudaFuncAttributeMaxDynamicSharedMemorySize, SMEM_BYTES);
    din_user_rep_mma<<<NB, 256, SMEM_BYTES>>>(
        (const float*)d_in[0],  // em
        (const float*)d_in[1],  // eu
        (const float*)d_in[2],  // Xu
        (const float*)d_in[3],  // W1
        (const float*)d_in[4],  // b1
        (const float*)d_in[5],  // W2
        (const float*)d_in[6],  // b2
        (const float*)d_in[7],  // W3
        (const float*)d_in[8],  // b3
        (const float*)d_in[9],  // gamma
        (const float*)d_in[10], // beta
        (const float*)d_in[11], // mov_mean
        (const float*)d_in[12], // mov_var
        (float*)d_out);
}

// round 12
// speedup vs baseline: 2.3869x; 1.3816x over previous
#include <cuda_runtime.h>
#include <cuda_bf16.h>
#include <cstdint>

// Fixed shapes
#define NB 4096
#define NS 200
#define SA 144        // row stride (bytes) for all mma tiles; 16B-aligned, conflict-free

// smem layout (bytes)
#define OFF_AHI   0        // X hi bf16: 208 rows x 144B  (29952)
#define OFF_ALO   29952    // X lo
#define OFF_B1HI  59904    // M_b^T hi: 64 rows x 144B    (9216)
#define OFF_B1LO  69120
#define OFF_B2HI  78336    // W2^T hi: 32 rows x 144B     (4608)
#define OFF_B2LO  82944
#define OFF_QS    87552    // 64 f
#define OFF_CS    87808    // 64 f (c_b)
#define OFF_B2S   88064    // 32 f
#define OFF_W3S   88192    // 32 f
#define OFF_BNSC  88320    // 128 f
#define OFF_BNSH  88832    // 128 f
#define OFF_LG    89344    // 200 f
#define OFF_WE    90144    // 200 f
#define OFF_PP    90944    // 256 f
#define OFF_RED   91968    // red[2]=b3, red[0]=max, red[1]=1/sum
#define SMEM_BYTES 92032

static __device__ __forceinline__ uint32_t s2u(const void* p) {
    uint32_t a;
    asm("{ .reg .u64 t; cvta.to.shared.u64 t, %1; cvt.u32.u64 %0, t; }"
        : "=r"(a) : "l"(p));
    return a;
}

#define LDSM_X4(r0, r1, r2, r3, addr) \
    asm volatile("ldmatrix.sync.aligned.m8n8.x4.shared.b16 {%0,%1,%2,%3}, [%4];" \
                 : "=r"(r0), "=r"(r1), "=r"(r2), "=r"(r3) : "r"(addr))
#define LDSM_X2(r0, r1, addr) \
    asm volatile("ldmatrix.sync.aligned.m8n8.x2.shared.b16 {%0,%1}, [%2];" \
                 : "=r"(r0), "=r"(r1) : "r"(addr))
#define MMA_BF16(c, a0, a1, a2, a3, b0, b1) \
    asm volatile("mma.sync.aligned.m16n8k16.row.col.f32.bf16.bf16.f32 " \
                 "{%0,%1,%2,%3}, {%4,%5,%6,%7}, {%8,%9}, {%0,%1,%2,%3};" \
                 : "+f"((c)[0]), "+f"((c)[1]), "+f"((c)[2]), "+f"((c)[3]) \
                 : "r"(a0), "r"(a1), "r"(a2), "r"(a3), "r"(b0), "r"(b1))

// split pair (x, y) -> packed bf16x2 hi word + lo (residual) word
static __device__ __forceinline__ void split2(float x, float y,
                                              uint32_t& h, uint32_t& l) {
    __nv_bfloat16 xh = __float2bfloat16(x), yh = __float2bfloat16(y);
    __nv_bfloat16 xl = __float2bfloat16(x - __bfloat162float(xh));
    __nv_bfloat16 yl = __float2bfloat16(y - __bfloat162float(yh));
    h = (uint32_t)__bfloat16_as_ushort(xh) | ((uint32_t)__bfloat16_as_ushort(yh) << 16);
    l = (uint32_t)__bfloat16_as_ushort(xl) | ((uint32_t)__bfloat16_as_ushort(yl) << 16);
}

extern __shared__ unsigned char smem_raw[];

__global__ void __launch_bounds__(256, 2) din_user_rep_mma(
    const float* __restrict__ em,   const float* __restrict__ eu,
    const float* __restrict__ Xu,   const float* __restrict__ W1,
    const float* __restrict__ b1,   const float* __restrict__ W2,
    const float* __restrict__ b2,   const float* __restrict__ W3,
    const float* __restrict__ b3,   const float* __restrict__ gamma,
    const float* __restrict__ beta, const float* __restrict__ mmean,
    const float* __restrict__ mvar, float* __restrict__ out)
{
    const int t = threadIdx.x;
    const int b = blockIdx.x;
    const uint32_t sb = s2u(smem_raw);

    float* qs   = (float*)(smem_raw + OFF_QS);
    float* cs   = (float*)(smem_raw + OFF_CS);
    float* b2s  = (float*)(smem_raw + OFF_B2S);
    float* w3s  = (float*)(smem_raw + OFF_W3S);
    float* bnsc = (float*)(smem_raw + OFF_BNSC);
    float* bnsh = (float*)(smem_raw + OFF_BNSH);
    float* lg   = (float*)(smem_raw + OFF_LG);
    float* we   = (float*)(smem_raw + OFF_WE);
    float* pp   = (float*)(smem_raw + OFF_PP);
    float* red  = (float*)(smem_raw + OFF_RED);

    const int wid = t >> 5;

    // ================= Phase A: all staging, ONE barrier =================
    if (t < 64)  qs[t] = em[(size_t)b * 64 + t];
    if (t < 128) {
        float sc = gamma[t] * rsqrtf(mvar[t] + 1e-3f);
        bnsc[t] = sc;
        bnsh[t] = beta[t] - mmean[t] * sc;
    }
    if (t < 32) { w3s[t] = W3[t]; b2s[t] = b2[t]; }
    if (t == 0) red[2] = b3[0];

    if (wid == 7) {
        // ---- dedicated c_b warp: c_b = b1 + q @ (W1a + W1c) ----
        const int lane = t & 31;
        float c0 = b1[lane], c1 = b1[lane + 32];
        const float* emb = em + (size_t)b * 64;
        #pragma unroll 8
        for (int k = 0; k < 64; k++) {
            float qk = emb[k];
            c0 += qk * (W1[k * 64 + lane]        + W1[(128 + k) * 64 + lane]);
            c1 += qk * (W1[k * 64 + lane + 32]   + W1[(128 + k) * 64 + lane + 32]);
        }
        cs[lane] = c0;
        cs[lane + 32] = c1;
    } else {
        // ---- warps 0-6 (224 threads): Xu staging, W1 fold, W2, pad ----
        // Xu: coalesced float4 read -> bf16 hi/lo pairs
        const float4* Xb4 = (const float4*)(Xu + (size_t)b * (NS * 64));
        #pragma unroll 2
        for (int e = t; e < NS * 16; e += 224) {
            int s = e >> 4, c4 = e & 15;
            float4 xv = Xb4[e];
            uint32_t h0, l0, h1, l1;
            split2(xv.x, xv.y, h0, l0);
            split2(xv.z, xv.w, h1, l1);
            *(uint2*)(smem_raw + OFF_AHI + s * SA + c4 * 8) = make_uint2(h0, h1);
            *(uint2*)(smem_raw + OFF_ALO + s * SA + c4 * 8) = make_uint2(l0, l1);
        }
        // B1t[j][k] = M_b^T fold (em read direct from global; L1 broadcast)
        const float* emb = em + (size_t)b * 64;
        #pragma unroll 4
        for (int e = t; e < 4096; e += 224) {
            int j = e & 63, k = e >> 6;             // coalesced W1 reads
            float m = W1[(64 + k) * 64 + j] - W1[(128 + k) * 64 + j]
                    + emb[k] * W1[(192 + k) * 64 + j];
            __nv_bfloat16 mh = __float2bfloat16(m);
            __nv_bfloat16 ml = __float2bfloat16(m - __bfloat162float(mh));
            *(uint16_t*)(smem_raw + OFF_B1HI + j * SA + k * 2) = __bfloat16_as_ushort(mh);
            *(uint16_t*)(smem_raw + OFF_B1LO + j * SA + k * 2) = __bfloat16_as_ushort(ml);
        }
        // B2t[j2][k] = W2[k][j2], bf16 hi/lo
        #pragma unroll 2
        for (int e = t; e < 2048; e += 224) {
            int j2 = e & 31, k = e >> 5;            // coalesced W2 read
            float w = W2[k * 32 + j2];
            __nv_bfloat16 wh = __float2bfloat16(w);
            __nv_bfloat16 wl = __float2bfloat16(w - __bfloat162float(wh));
            *(uint16_t*)(smem_raw + OFF_B2HI + j2 * SA + k * 2) = __bfloat16_as_ushort(wh);
            *(uint16_t*)(smem_raw + OFF_B2LO + j2 * SA + k * 2) = __bfloat16_as_ushort(wl);
        }
        // zero pad A rows 200..207 (first 32 words of each row)
        for (int e = t; e < 512; e += 224) {
            int reg = e >> 8, w = e & 255;
            int r = 200 + (w >> 5), c = w & 31;
            uint32_t off = (reg ? OFF_ALO : OFF_AHI) + r * SA + c * 4;
            *(uint32_t*)(smem_raw + off) = 0;
        }
    }
    __syncthreads();

    // ---- Per-warp MLP over 16-row m-tiles (13 tiles, warps independent) ----
    {
        const int lane = t & 31;
        const int kp = lane & 3, rq = lane >> 2;
        const uint32_t aRow = (uint32_t)(((lane & 7) + 8 * ((lane >> 3) & 1)) * SA
                                         + (lane >> 4) * 16);
        const uint32_t bRow = (uint32_t)((lane & 7) * SA + ((lane >> 3) & 1) * 16);
        const float b3v = red[2];

        for (int tile = wid; tile < 13; tile += 8) {
            const int m0 = tile * 16;
            const uint32_t aH = sb + OFF_AHI + m0 * SA + aRow;
            const uint32_t aL = sb + OFF_ALO + m0 * SA + aRow;
            const uint32_t bH = sb + OFF_B1HI + bRow;
            const uint32_t bL = sb + OFF_B1LO + bRow;

            // Layer 1: C1[16 x 64] = X_tile @ M_b  (3-term bf16 split)
            float acc[8][4];
            #pragma unroll
            for (int nt = 0; nt < 8; nt++)
                #pragma unroll
                for (int i = 0; i < 4; i++) acc[nt][i] = 0.f;

            #pragma unroll
            for (int kc = 0; kc < 4; kc++) {
                uint32_t ah0, ah1, ah2, ah3, al0, al1, al2, al3;
                LDSM_X4(ah0, ah1, ah2, ah3, aH + kc * 32);
                LDSM_X4(al0, al1, al2, al3, aL + kc * 32);
                #pragma unroll
                for (int nt = 0; nt < 8; nt++) {
                    uint32_t bh0, bh1, bl0, bl1;
                    LDSM_X2(bh0, bh1, bH + nt * (8 * SA) + kc * 32);
                    LDSM_X2(bl0, bl1, bL + nt * (8 * SA) + kc * 32);
                    MMA_BF16(acc[nt], ah0, ah1, ah2, ah3, bh0, bh1);
                    MMA_BF16(acc[nt], ah0, ah1, ah2, ah3, bl0, bl1);
                    MMA_BF16(acc[nt], al0, al1, al2, al3, bh0, bh1);
                }
            }

            // Epilogue 1 (registers): h1 = relu(C1 + c_b) -> layer-2 A frags
            uint32_t hH[8][2], hL[8][2];
            #pragma unroll
            for (int nt = 0; nt < 8; nt++) {
                int j0 = 8 * nt + 2 * kp;
                float c0 = cs[j0], c1 = cs[j0 + 1];
                float e0 = fmaxf(acc[nt][0] + c0, 0.f);
                float e1 = fmaxf(acc[nt][1] + c1, 0.f);
                float e2 = fmaxf(acc[nt][2] + c0, 0.f);
                float e3 = fmaxf(acc[nt][3] + c1, 0.f);
                split2(e0, e1, hH[nt][0], hL[nt][0]);   // row r
                split2(e2, e3, hH[nt][1], hL[nt][1]);   // row r+8
            }

            // Layer 2: C2[16 x 32] = h1 @ W2 (A frags direct from registers)
            float a2c[4][4];
            #pragma unroll
            for (int nt = 0; nt < 4; nt++)
                #pragma unroll
                for (int i = 0; i < 4; i++) a2c[nt][i] = 0.f;

            const uint32_t c2H = sb + OFF_B2HI + bRow;
            const uint32_t c2L = sb + OFF_B2LO + bRow;
            #pragma unroll
            for (int kc = 0; kc < 4; kc++) {
                uint32_t a0h = hH[2 * kc][0], a1h = hH[2 * kc][1];
                uint32_t a2h = hH[2 * kc + 1][0], a3h = hH[2 * kc + 1][1];
                uint32_t a0l = hL[2 * kc][0], a1l = hL[2 * kc][1];
                uint32_t a2l = hL[2 * kc + 1][0], a3l = hL[2 * kc + 1][1];
                #pragma unroll
                for (int nt = 0; nt < 4; nt++) {
                    uint32_t bh0, bh1, bl0, bl1;
                    LDSM_X2(bh0, bh1, c2H + nt * (8 * SA) + kc * 32);
                    LDSM_X2(bl0, bl1, c2L + nt * (8 * SA) + kc * 32);
                    MMA_BF16(a2c[nt], a0h, a1h, a2h, a3h, bh0, bh1);
                    MMA_BF16(a2c[nt], a0h, a1h, a2h, a3h, bl0, bl1);
                    MMA_BF16(a2c[nt], a0l, a1l, a2l, a3l, bh0, bh1);
                }
            }

            // Epilogue 2: logits (quad reduce over kp lanes)
            float pA = 0.f, pB = 0.f;
            #pragma unroll
            for (int nt = 0; nt < 4; nt++) {
                int j0 = 8 * nt + 2 * kp;
                float bb0 = b2s[j0], bb1 = b2s[j0 + 1];
                float w0 = w3s[j0],  w1 = w3s[j0 + 1];
                pA += fmaxf(a2c[nt][0] + bb0, 0.f) * w0
                    + fmaxf(a2c[nt][1] + bb1, 0.f) * w1;
                pB += fmaxf(a2c[nt][2] + bb0, 0.f) * w0
                    + fmaxf(a2c[nt][3] + bb1, 0.f) * w1;
            }
            pA += __shfl_xor_sync(0xffffffffu, pA, 1);
            pA += __shfl_xor_sync(0xffffffffu, pA, 2);
            pB += __shfl_xor_sync(0xffffffffu, pB, 1);
            pB += __shfl_xor_sync(0xffffffffu, pB, 2);
            if (kp == 0) {
                int r0_ = m0 + rq;
                int r1_ = m0 + rq + 8;
                if (r0_ < NS) lg[r0_] = pA + b3v;
                if (r1_ < NS) lg[r1_] = pB + b3v;
            }
        }
    }
    __syncthreads();

    // ---- Softmax (warp 0) ----
    if (t < 32) {
        float m = -3.0e38f;
        for (int r = t; r < NS; r += 32) m = fmaxf(m, lg[r]);
        #pragma unroll
        for (int o = 16; o; o >>= 1) m = fmaxf(m, __shfl_xor_sync(0xffffffffu, m, o));
        float ssum = 0.f;
        for (int r = t; r < NS; r += 32) ssum += __expf(lg[r] - m);
        #pragma unroll
        for (int o = 16; o; o >>= 1) ssum += __shfl_xor_sync(0xffffffffu, ssum, o);
        if (t == 0) { red[0] = m; red[1] = 1.f / ssum; }
    }
    __syncthreads();
    if (t < NS) we[t] = __expf(lg[t] - red[0]) * red[1];
    __syncthreads();

    // ---- Pool from reconstructed X (hi+lo, exact to ~2^-17) ----
    {
        int d = t & 63, q = t >> 6;
        float p = 0.f;
        #pragma unroll 2
        for (int s = 50 * q; s < 50 * q + 50; s++) {
            uint16_t h = *(const uint16_t*)(smem_raw + OFF_AHI + s * SA + 2 * d);
            uint16_t l = *(const uint16_t*)(smem_raw + OFF_ALO + s * SA + 2 * d);
            float x = __bfloat162float(__ushort_as_bfloat16(h))
                    + __bfloat162float(__ushort_as_bfloat16(l));
            p += we[s] * x;
        }
        pp[t] = p;
    }
    __syncthreads();

    // ---- Output: [bn(pooled), bn(em), eu] ----
    float* ob = out + (size_t)b * 192;
    if (t < 64) {
        float pooled = pp[t] + pp[t + 64] + pp[t + 128] + pp[t + 192];
        ob[t] = pooled * bnsc[t] + bnsh[t];
    } else if (t < 128) {
        ob[t] = qs[t - 64] * bnsc[t] + bnsh[t];
    } else if (t < 192) {
        ob[t] = eu[(size_t)b * 64 + (t - 128)];
    }
}

extern "C" void kernel_launch(void* const* d_in, const int* in_sizes, int n_in,
                              void* d_out, int out_size) {
    (void)in_sizes; (void)n_in; (void)out_size;
    cudaFuncSetAttribute(din_user_rep_mma,
                         cudaFuncAttributeMaxDynamicSharedMemorySize, SMEM_BYTES);
    din_user_rep_mma<<<NB, 256, SMEM_BYTES>>>(
        (const float*)d_in[0],  // em
        (const float*)d_in[1],  // eu
        (const float*)d_in[2],  // Xu
        (const float*)d_in[3],  // W1
        (const float*)d_in[4],  // b1
        (const float*)d_in[5],  // W2
        (const float*)d_in[6],  // b2
        (const float*)d_in[7],  // W3
        (const float*)d_in[8],  // b3
        (const float*)d_in[9],  // gamma
        (const float*)d_in[10], // beta
        (const float*)d_in[11], // mov_mean
        (const float*)d_in[12], // mov_var
        (float*)d_out);
}

// round 14
// speedup vs baseline: 2.6551x; 1.1123x over previous
#include <cuda_runtime.h>
#include <cuda_bf16.h>
#include <cstdint>

// Fixed shapes
#define NB 4096
#define NS 200
#define SA 144        // row stride (bytes) for all mma tiles; 16B-aligned, conflict-free

// smem layout (bytes)
#define OFF_AHI   0        // X hi bf16: 208 rows x 144B  (29952)
#define OFF_ALO   29952    // X lo
#define OFF_B1HI  59904    // M_b^T hi: 64 rows x 144B    (9216)
#define OFF_B1LO  69120
#define OFF_B2HI  78336    // W2^T hi: 32 rows x 144B     (4608)
#define OFF_B2LO  82944
#define OFF_QS    87552    // 64 f
#define OFF_CS    87808    // 64 f (c_b)
#define OFF_B2S   88064    // 32 f
#define OFF_W3S   88192    // 32 f
#define OFF_BNSC  88320    // 128 f
#define OFF_BNSH  88832    // 128 f
#define OFF_LG    89344    // 200 f
#define OFF_WE    90144    // 200 f
#define OFF_PP    90944    // 256 float2 = 2048
#define OFF_RED   92992    // red[2]=b3, red[0]=max, red[1]=1/sum
#define SMEM_BYTES 93056

static __device__ __forceinline__ uint32_t s2u(const void* p) {
    uint32_t a;
    asm("{ .reg .u64 t; cvta.to.shared.u64 t, %1; cvt.u32.u64 %0, t; }"
        : "=r"(a) : "l"(p));
    return a;
}

#define LDSM_X4(r0, r1, r2, r3, addr) \
    asm volatile("ldmatrix.sync.aligned.m8n8.x4.shared.b16 {%0,%1,%2,%3}, [%4];" \
                 : "=r"(r0), "=r"(r1), "=r"(r2), "=r"(r3) : "r"(addr))
#define MMA_BF16(c, a0, a1, a2, a3, b0, b1) \
    asm volatile("mma.sync.aligned.m16n8k16.row.col.f32.bf16.bf16.f32 " \
                 "{%0,%1,%2,%3}, {%4,%5,%6,%7}, {%8,%9}, {%0,%1,%2,%3};" \
                 : "+f"((c)[0]), "+f"((c)[1]), "+f"((c)[2]), "+f"((c)[3]) \
                 : "r"(a0), "r"(a1), "r"(a2), "r"(a3), "r"(b0), "r"(b1))

// split pair (x, y) -> packed bf16x2 hi word + lo (residual) word
static __device__ __forceinline__ void split2(float x, float y,
                                              uint32_t& h, uint32_t& l) {
    __nv_bfloat16 xh = __float2bfloat16(x), yh = __float2bfloat16(y);
    __nv_bfloat16 xl = __float2bfloat16(x - __bfloat162float(xh));
    __nv_bfloat16 yl = __float2bfloat16(y - __bfloat162float(yh));
    h = (uint32_t)__bfloat16_as_ushort(xh) | ((uint32_t)__bfloat16_as_ushort(yh) << 16);
    l = (uint32_t)__bfloat16_as_ushort(xl) | ((uint32_t)__bfloat16_as_ushort(yl) << 16);
}
// split one value -> hi/lo ushorts
static __device__ __forceinline__ void split1(float x, uint16_t& h, uint16_t& l) {
    __nv_bfloat16 xh = __float2bfloat16(x);
    __nv_bfloat16 xl = __float2bfloat16(x - __bfloat162float(xh));
    h = __bfloat16_as_ushort(xh);
    l = __bfloat16_as_ushort(xl);
}

extern __shared__ unsigned char smem_raw[];

__global__ void __launch_bounds__(256, 2) din_user_rep_mma(
    const float* __restrict__ em,   const float* __restrict__ eu,
    const float* __restrict__ Xu,   const float* __restrict__ W1,
    const float* __restrict__ b1,   const float* __restrict__ W2,
    const float* __restrict__ b2,   const float* __restrict__ W3,
    const float* __restrict__ b3,   const float* __restrict__ gamma,
    const float* __restrict__ beta, const float* __restrict__ mmean,
    const float* __restrict__ mvar, float* __restrict__ out)
{
    const int t = threadIdx.x;
    const int b = blockIdx.x;
    const uint32_t sb = s2u(smem_raw);

    float* qs   = (float*)(smem_raw + OFF_QS);
    float* cs   = (float*)(smem_raw + OFF_CS);
    float* b2s  = (float*)(smem_raw + OFF_B2S);
    float* w3s  = (float*)(smem_raw + OFF_W3S);
    float* bnsc = (float*)(smem_raw + OFF_BNSC);
    float* bnsh = (float*)(smem_raw + OFF_BNSH);
    float* lg   = (float*)(smem_raw + OFF_LG);
    float* we   = (float*)(smem_raw + OFF_WE);
    float2* pp  = (float2*)(smem_raw + OFF_PP);
    float* red  = (float*)(smem_raw + OFF_RED);

    const int wid = t >> 5;

    // ================= Phase A: all staging, ONE barrier =================
    if (t < 64)  qs[t] = em[(size_t)b * 64 + t];
    if (t < 128) {
        float sc = gamma[t] * rsqrtf(mvar[t] + 1e-3f);
        bnsc[t] = sc;
        bnsh[t] = beta[t] - mmean[t] * sc;
    }
    if (t < 32) { w3s[t] = W3[t]; b2s[t] = b2[t]; }
    if (t == 0) red[2] = b3[0];

    if (wid == 7) {
        // ---- dedicated c_b warp: c_b = b1 + q @ (W1a + W1c) ----
        const int lane = t & 31;
        float c0 = b1[lane], c1 = b1[lane + 32];
        const float* emb = em + (size_t)b * 64;
        #pragma unroll 8
        for (int k = 0; k < 64; k++) {
            float qk = emb[k];
            c0 += qk * (W1[k * 64 + lane]      + W1[(128 + k) * 64 + lane]);
            c1 += qk * (W1[k * 64 + lane + 32] + W1[(128 + k) * 64 + lane + 32]);
        }
        cs[lane] = c0;
        cs[lane + 32] = c1;
    } else {
        // ---- warps 0-6 (224 threads): Xu staging, W1 fold, W2, pad ----
        const float4* Xb4 = (const float4*)(Xu + (size_t)b * (NS * 64));
        #pragma unroll 2
        for (int e = t; e < NS * 16; e += 224) {
            int s = e >> 4, c4 = e & 15;
            float4 xv = Xb4[e];
            uint32_t h0, l0, h1, l1;
            split2(xv.x, xv.y, h0, l0);
            split2(xv.z, xv.w, h1, l1);
            *(uint2*)(smem_raw + OFF_AHI + s * SA + c4 * 8) = make_uint2(h0, h1);
            *(uint2*)(smem_raw + OFF_ALO + s * SA + c4 * 8) = make_uint2(l0, l1);
        }
        // B1t[j][k] = M_b^T fold, paired k -> 32-bit stores
        const float* emb = em + (size_t)b * 64;
        #pragma unroll 4
        for (int e = t; e < 2048; e += 224) {
            int j = e & 63, k = (e >> 6) * 2;
            float q0 = emb[k], q1 = emb[k + 1];
            float m0v = W1[(64 + k) * 64 + j] - W1[(128 + k) * 64 + j]
                      + q0 * W1[(192 + k) * 64 + j];
            float m1v = W1[(65 + k) * 64 + j] - W1[(129 + k) * 64 + j]
                      + q1 * W1[(193 + k) * 64 + j];
            uint16_t h0, l0, h1, l1;
            split1(m0v, h0, l0);
            split1(m1v, h1, l1);
            *(uint32_t*)(smem_raw + OFF_B1HI + j * SA + k * 2) =
                (uint32_t)h0 | ((uint32_t)h1 << 16);
            *(uint32_t*)(smem_raw + OFF_B1LO + j * SA + k * 2) =
                (uint32_t)l0 | ((uint32_t)l1 << 16);
        }
        // B2t[j2][k] = W2[k][j2], paired k
        #pragma unroll 2
        for (int e = t; e < 1024; e += 224) {
            int j2 = e & 31, k = (e >> 5) * 2;
            uint16_t h0, l0, h1, l1;
            split1(W2[k * 32 + j2], h0, l0);
            split1(W2[(k + 1) * 32 + j2], h1, l1);
            *(uint32_t*)(smem_raw + OFF_B2HI + j2 * SA + k * 2) =
                (uint32_t)h0 | ((uint32_t)h1 << 16);
            *(uint32_t*)(smem_raw + OFF_B2LO + j2 * SA + k * 2) =
                (uint32_t)l0 | ((uint32_t)l1 << 16);
        }
        // zero pad A rows 200..207
        for (int e = t; e < 512; e += 224) {
            int reg = e >> 8, w = e & 255;
            int r = 200 + (w >> 5), c = w & 31;
            uint32_t off = (reg ? OFF_ALO : OFF_AHI) + r * SA + c * 4;
            *(uint32_t*)(smem_raw + off) = 0;
        }
    }
    __syncthreads();

    // ---- Per-warp MLP; dual-tile layer 1 shares B1 fragment loads ----
    {
        const int lane = t & 31;
        const int kp = lane & 3, rq = lane >> 2;
        // A frags: m16 x k16 ldmatrix.x4 addressing
        const uint32_t aRow = (uint32_t)(((lane & 7) + 8 * ((lane >> 3) & 1)) * SA
                                         + (lane >> 4) * 16);
        // B frags: n16 x k16 ldmatrix.x4 addressing (matrices: n0-7/k0-7,
        // n0-7/k8-15, n8-15/k0-7, n8-15/k8-15)
        const uint32_t bRow4 = (uint32_t)(((lane & 7) + 8 * ((lane >> 4) & 1)) * SA
                                          + ((lane >> 3) & 1) * 16);
        const float b3v = red[2];
        const bool has2 = (wid < 5);
        const int m0 = wid * 16, m1 = (wid + 8) * 16;

        float acc0[8][4], acc1[8][4];
        #pragma unroll
        for (int nt = 0; nt < 8; nt++)
            #pragma unroll
            for (int i = 0; i < 4; i++) { acc0[nt][i] = 0.f; acc1[nt][i] = 0.f; }

        const uint32_t a0H = sb + OFF_AHI + m0 * SA + aRow;
        const uint32_t a0L = sb + OFF_ALO + m0 * SA + aRow;
        const uint32_t a1H = sb + OFF_AHI + m1 * SA + aRow;
        const uint32_t a1L = sb + OFF_ALO + m1 * SA + aRow;
        const uint32_t b1H = sb + OFF_B1HI + bRow4;
        const uint32_t b1L = sb + OFF_B1LO + bRow4;

        #pragma unroll
        for (int kc = 0; kc < 4; kc++) {
            uint32_t Ah0[4], Al0[4], Ah1[4], Al1[4];
            LDSM_X4(Ah0[0], Ah0[1], Ah0[2], Ah0[3], a0H + kc * 32);
            LDSM_X4(Al0[0], Al0[1], Al0[2], Al0[3], a0L + kc * 32);
            if (has2) {
                LDSM_X4(Ah1[0], Ah1[1], Ah1[2], Ah1[3], a1H + kc * 32);
                LDSM_X4(Al1[0], Al1[1], Al1[2], Al1[3], a1L + kc * 32);
            }
            #pragma unroll
            for (int ntp = 0; ntp < 4; ntp++) {
                uint32_t bh[4], bl[4];
                LDSM_X4(bh[0], bh[1], bh[2], bh[3], b1H + ntp * (16 * SA) + kc * 32);
                LDSM_X4(bl[0], bl[1], bl[2], bl[3], b1L + ntp * (16 * SA) + kc * 32);
                MMA_BF16(acc0[2 * ntp],     Ah0[0], Ah0[1], Ah0[2], Ah0[3], bh[0], bh[1]);
                MMA_BF16(acc0[2 * ntp + 1], Ah0[0], Ah0[1], Ah0[2], Ah0[3], bh[2], bh[3]);
                MMA_BF16(acc0[2 * ntp],     Ah0[0], Ah0[1], Ah0[2], Ah0[3], bl[0], bl[1]);
                MMA_BF16(acc0[2 * ntp + 1], Ah0[0], Ah0[1], Ah0[2], Ah0[3], bl[2], bl[3]);
                MMA_BF16(acc0[2 * ntp],     Al0[0], Al0[1], Al0[2], Al0[3], bh[0], bh[1]);
                MMA_BF16(acc0[2 * ntp + 1], Al0[0], Al0[1], Al0[2], Al0[3], bh[2], bh[3]);
                if (has2) {
                    MMA_BF16(acc1[2 * ntp],     Ah1[0], Ah1[1], Ah1[2], Ah1[3], bh[0], bh[1]);
                    MMA_BF16(acc1[2 * ntp + 1], Ah1[0], Ah1[1], Ah1[2], Ah1[3], bh[2], bh[3]);
                    MMA_BF16(acc1[2 * ntp],     Ah1[0], Ah1[1], Ah1[2], Ah1[3], bl[0], bl[1]);
                    MMA_BF16(acc1[2 * ntp + 1], Ah1[0], Ah1[1], Ah1[2], Ah1[3], bl[2], bl[3]);
                    MMA_BF16(acc1[2 * ntp],     Al1[0], Al1[1], Al1[2], Al1[3], bh[0], bh[1]);
                    MMA_BF16(acc1[2 * ntp + 1], Al1[0], Al1[1], Al1[2], Al1[3], bh[2], bh[3]);
                }
            }
        }

        // per-tile tail: epilogue1 -> layer2 -> logits
        auto tail = [&](float (&acc)[8][4], int mb) {
            uint32_t hH[8][2], hL[8][2];
            #pragma unroll
            for (int nt = 0; nt < 8; nt++) {
                int j0 = 8 * nt + 2 * kp;
                float c0 = cs[j0], c1 = cs[j0 + 1];
                float e0 = fmaxf(acc[nt][0] + c0, 0.f);
                float e1 = fmaxf(acc[nt][1] + c1, 0.f);
                float e2 = fmaxf(acc[nt][2] + c0, 0.f);
                float e3 = fmaxf(acc[nt][3] + c1, 0.f);
                split2(e0, e1, hH[nt][0], hL[nt][0]);
                split2(e2, e3, hH[nt][1], hL[nt][1]);
            }
            float a2c[4][4];
            #pragma unroll
            for (int nt = 0; nt < 4; nt++)
                #pragma unroll
                for (int i = 0; i < 4; i++) a2c[nt][i] = 0.f;

            const uint32_t c2H = sb + OFF_B2HI + bRow4;
            const uint32_t c2L = sb + OFF_B2LO + bRow4;
            #pragma unroll
            for (int kc = 0; kc < 4; kc++) {
                uint32_t a0h = hH[2 * kc][0], a1h = hH[2 * kc][1];
                uint32_t a2h = hH[2 * kc + 1][0], a3h = hH[2 * kc + 1][1];
                uint32_t a0l = hL[2 * kc][0], a1l = hL[2 * kc][1];
                uint32_t a2l = hL[2 * kc + 1][0], a3l = hL[2 * kc + 1][1];
                #pragma unroll
                for (int ntp = 0; ntp < 2; ntp++) {
                    uint32_t bh[4], bl[4];
                    LDSM_X4(bh[0], bh[1], bh[2], bh[3], c2H + ntp * (16 * SA) + kc * 32);
                    LDSM_X4(bl[0], bl[1], bl[2], bl[3], c2L + ntp * (16 * SA) + kc * 32);
                    MMA_BF16(a2c[2 * ntp],     a0h, a1h, a2h, a3h, bh[0], bh[1]);
                    MMA_BF16(a2c[2 * ntp + 1], a0h, a1h, a2h, a3h, bh[2], bh[3]);
                    MMA_BF16(a2c[2 * ntp],     a0h, a1h, a2h, a3h, bl[0], bl[1]);
                    MMA_BF16(a2c[2 * ntp + 1], a0h, a1h, a2h, a3h, bl[2], bl[3]);
                    MMA_BF16(a2c[2 * ntp],     a0l, a1l, a2l, a3l, bh[0], bh[1]);
                    MMA_BF16(a2c[2 * ntp + 1], a0l, a1l, a2l, a3l, bh[2], bh[3]);
                }
            }
            float pA = 0.f, pB = 0.f;
            #pragma unroll
            for (int nt = 0; nt < 4; nt++) {
                int j0 = 8 * nt + 2 * kp;
                float bb0 = b2s[j0], bb1 = b2s[j0 + 1];
                float w0 = w3s[j0],  w1 = w3s[j0 + 1];
                pA += fmaxf(a2c[nt][0] + bb0, 0.f) * w0
                    + fmaxf(a2c[nt][1] + bb1, 0.f) * w1;
                pB += fmaxf(a2c[nt][2] + bb0, 0.f) * w0
                    + fmaxf(a2c[nt][3] + bb1, 0.f) * w1;
            }
            pA += __shfl_xor_sync(0xffffffffu, pA, 1);
            pA += __shfl_xor_sync(0xffffffffu, pA, 2);
            pB += __shfl_xor_sync(0xffffffffu, pB, 1);
            pB += __shfl_xor_sync(0xffffffffu, pB, 2);
            if (kp == 0) {
                int r0_ = mb + rq, r1_ = mb + rq + 8;
                if (r0_ < NS) lg[r0_] = pA + b3v;
                if (r1_ < NS) lg[r1_] = pB + b3v;
            }
        };
        tail(acc0, m0);
        if (has2) tail(acc1, m1);
    }
    __syncthreads();

    // ---- Softmax (warp 0) ----
    if (t < 32) {
        float m = -3.0e38f;
        for (int r = t; r < NS; r += 32) m = fmaxf(m, lg[r]);
        #pragma unroll
        for (int o = 16; o; o >>= 1) m = fmaxf(m, __shfl_xor_sync(0xffffffffu, m, o));
        float ssum = 0.f;
        for (int r = t; r < NS; r += 32) ssum += __expf(lg[r] - m);
        #pragma unroll
        for (int o = 16; o; o >>= 1) ssum += __shfl_xor_sync(0xffffffffu, ssum, o);
        if (t == 0) { red[0] = m; red[1] = 1.f / ssum; }
    }
    __syncthreads();
    if (t < NS) we[t] = __expf(lg[t] - red[0]) * red[1];
    __syncthreads();

    // ---- Pool: d-pairs via 32-bit LDS, 8-way s-split ----
    {
        int dp = t & 31, q = t >> 5;           // d = 2dp, 2dp+1; s in [25q, 25q+25)
        float px = 0.f, py = 0.f;
        #pragma unroll 5
        for (int s = 25 * q; s < 25 * q + 25; s++) {
            uint32_t h = *(const uint32_t*)(smem_raw + OFF_AHI + s * SA + 4 * dp);
            uint32_t l = *(const uint32_t*)(smem_raw + OFF_ALO + s * SA + 4 * dp);
            float x0 = __bfloat162float(__ushort_as_bfloat16((uint16_t)h))
                     + __bfloat162float(__ushort_as_bfloat16((uint16_t)l));
            float x1 = __bfloat162float(__ushort_as_bfloat16((uint16_t)(h >> 16)))
                     + __bfloat162float(__ushort_as_bfloat16((uint16_t)(l >> 16)));
            float w = we[s];
            px += w * x0;
            py += w * x1;
        }
        pp[t] = make_float2(px, py);
    }
    __syncthreads();

    // ---- Output: [bn(pooled), bn(em), eu] ----
    float* ob = out + (size_t)b * 192;
    if (t < 64) {
        int dp = t >> 1, c = t & 1;
        float pooled = 0.f;
        #pragma unroll
        for (int q = 0; q < 8; q++) {
            float2 v = pp[q * 32 + dp];
            pooled += c ? v.y : v.x;
        }
        ob[t] = pooled * bnsc[t] + bnsh[t];
    } else if (t < 128) {
        ob[t] = qs[t - 64] * bnsc[t] + bnsh[t];
    } else if (t < 192) {
        ob[t] = eu[(size_t)b * 64 + (t - 128)];
    }
}

extern "C" void kernel_launch(void* const* d_in, const int* in_sizes, int n_in,
                              void* d_out, int out_size) {
    (void)in_sizes; (void)n_in; (void)out_size;
    cudaFuncSetAttribute(din_user_rep_mma,
                         cudaFuncAttributeMaxDynamicSharedMemorySize, SMEM_BYTES);
    din_user_rep_mma<<<NB, 256, SMEM_BYTES>>>(
        (const float*)d_in[0],  // em
        (const float*)d_in[1],  // eu
        (const float*)d_in[2],  // Xu
        (const float*)d_in[3],  // W1
        (const float*)d_in[4],  // b1
        (const float*)d_in[5],  // W2
        (const float*)d_in[6],  // b2
        (const float*)d_in[7],  // W3
        (const float*)d_in[8],  // b3
        (const float*)d_in[9],  // gamma
        (const float*)d_in[10], // beta
        (const float*)d_in[11], // mov_mean
        (const float*)d_in[12], // mov_var
        (float*)d_out);
}